// round 12
// baseline (speedup 1.0000x reference)
#include <cuda_runtime.h>
#include <math.h>

#define E      2048
#define TT     1024
#define BATCH  2
#define MROWS  (BATCH * TT)   // 2048
#define NKV    8
#define NQ     32
#define HD     64
#define KVW    (NKV * HD)     // 512

// ---------------- scratch (device globals; no allocations allowed) -------
__device__ float g_q[MROWS * E];     // 16 MB
__device__ float g_k[MROWS * KVW];   //  4 MB
__device__ float g_v[MROWS * KVW];   //  4 MB
__device__ float g_att[MROWS * E];   // 16 MB

// ---------------- SGEMM: C = A(MxK) * B(KxN) + bias, row-major ----------
// BM=BN=128, BK=16, 256 threads, 8x8 per-thread micro-tile.
// All problem dims are multiples of the tile sizes -> no bounds checks.
__global__ __launch_bounds__(256)
void sgemm_bias(const float* __restrict__ A, const float* __restrict__ B,
                const float* __restrict__ bias, float* __restrict__ C,
                int M, int N, int K)
{
    __shared__ float As[16][128];   // transposed: As[k][m]
    __shared__ float Bs[16][128];   // natural:    Bs[k][n]

    const int m0  = blockIdx.y * 128;
    const int n0  = blockIdx.x * 128;
    const int tid = threadIdx.x;
    const int tx  = tid & 15;       // 0..15 -> 8 output cols
    const int ty  = tid >> 4;       // 0..15 -> 8 output rows

    const int arow = tid >> 2;          // 0..63
    const int akc  = (tid & 3) << 2;    // 0,4,8,12
    const int brow = tid >> 5;          // 0..7
    const int bcol = (tid & 31) << 2;   // 0..124

    float acc[8][8];
#pragma unroll
    for (int i = 0; i < 8; i++)
#pragma unroll
        for (int j = 0; j < 8; j++) acc[i][j] = 0.f;

    for (int k0 = 0; k0 < K; k0 += 16) {
        // stage global tile into registers
        float4 a0 = *(const float4*)(A + (size_t)(m0 + arow)      * K + k0 + akc);
        float4 a1 = *(const float4*)(A + (size_t)(m0 + arow + 64) * K + k0 + akc);
        float4 b0 = *(const float4*)(B + (size_t)(k0 + brow)      * N + n0 + bcol);
        float4 b1 = *(const float4*)(B + (size_t)(k0 + brow + 8)  * N + n0 + bcol);

        __syncthreads();  // previous tile fully consumed
        As[akc + 0][arow]      = a0.x; As[akc + 1][arow]      = a0.y;
        As[akc + 2][arow]      = a0.z; As[akc + 3][arow]      = a0.w;
        As[akc + 0][arow + 64] = a1.x; As[akc + 1][arow + 64] = a1.y;
        As[akc + 2][arow + 64] = a1.z; As[akc + 3][arow + 64] = a1.w;
        *(float4*)&Bs[brow][bcol]     = b0;
        *(float4*)&Bs[brow + 8][bcol] = b1;
        __syncthreads();

#pragma unroll
        for (int kk = 0; kk < 16; ++kk) {
            float af[8], bf[8];
            float4 t0 = *(const float4*)&As[kk][ty * 8];
            float4 t1 = *(const float4*)&As[kk][ty * 8 + 4];
            float4 u0 = *(const float4*)&Bs[kk][tx * 8];
            float4 u1 = *(const float4*)&Bs[kk][tx * 8 + 4];
            af[0]=t0.x; af[1]=t0.y; af[2]=t0.z; af[3]=t0.w;
            af[4]=t1.x; af[5]=t1.y; af[6]=t1.z; af[7]=t1.w;
            bf[0]=u0.x; bf[1]=u0.y; bf[2]=u0.z; bf[3]=u0.w;
            bf[4]=u1.x; bf[5]=u1.y; bf[6]=u1.z; bf[7]=u1.w;
#pragma unroll
            for (int i = 0; i < 8; i++)
#pragma unroll
                for (int j = 0; j < 8; j++)
                    acc[i][j] = fmaf(af[i], bf[j], acc[i][j]);
        }
    }

    float bs[8];
#pragma unroll
    for (int j = 0; j < 8; j++) bs[j] = bias[n0 + tx * 8 + j];

#pragma unroll
    for (int i = 0; i < 8; i++) {
        const size_t r = (size_t)(m0 + ty * 8 + i) * N + n0 + tx * 8;
        float4 o0, o1;
        o0.x = acc[i][0] + bs[0]; o0.y = acc[i][1] + bs[1];
        o0.z = acc[i][2] + bs[2]; o0.w = acc[i][3] + bs[3];
        o1.x = acc[i][4] + bs[4]; o1.y = acc[i][5] + bs[5];
        o1.z = acc[i][6] + bs[6]; o1.w = acc[i][7] + bs[7];
        *(float4*)(C + r)     = o0;
        *(float4*)(C + r + 4) = o1;
    }
}

// ---------------- RoPE (in-place, rotate-half, pos = (t%1024)+1) --------
__global__ void rope_kernel(float* __restrict__ q, int width, int npairs)
{
    int p = blockIdx.x * blockDim.x + threadIdx.x;
    if (p >= npairs) return;
    const int half = width >> 1;       // pairs per row
    const int row  = p / half;
    const int rem  = p - row * half;
    const int head = rem >> 5;         // HD/2 = 32 pairs per head
    const int c    = rem & 31;
    const int base = row * width + head * HD + c;

    float x0 = q[base];
    float x1 = q[base + 32];
    float pos   = (float)((row & (TT - 1)) + 1);
    float theta = 1.0f / powf(10000.0f, (float)c * (1.0f / 32.0f));
    float ang   = pos * theta;
    float s, co;
    sincosf(ang, &s, &co);
    q[base]      = x0 * co - x1 * s;
    q[base + 32] = x1 * co + x0 * s;
}

// ---------------- Flash attention: 64x64 tiles, fp32 --------------------
// grid: (qblock 16, head 32, batch 2); 256 threads; 4x4 micro-tile.
// SMEM: Qs[64][64] transposed (d-major), Ks[64][65] (also reused for P),
//       Vs[64][64]. Softmax stats live in registers, replicated across the
//       16 lanes of each row-group via shfl butterflies.
#define ATTN_SMEM ((64 * 64 + 64 * 65 + 64 * 64) * 4)

__global__ __launch_bounds__(256)
void attn_kernel(const float* __restrict__ q, const float* __restrict__ k,
                 const float* __restrict__ v, float* __restrict__ o)
{
    extern __shared__ float sm[];
    float* Qs = sm;                 // [64][64]  Qs[d*64 + m]
    float* Ks = sm + 64 * 64;       // [64][65]  Ks[c*65 + d]  (later P[r*65+c])
    float* Vs = Ks + 64 * 65;       // [64][64]  Vs[kk*64 + d]

    const int qb  = blockIdx.x;     // 0..15
    const int h   = blockIdx.y;     // 0..31
    const int bb  = blockIdx.z;     // 0..1
    const int kvh = h >> 2;
    const int tid = threadIdx.x;
    const int tx  = tid & 15;
    const int ty  = tid >> 4;
    const int r0  = ty << 2;        // 4 query rows
    const int c0  = tx << 2;        // 4 key cols / 4 out dims
    const int qrow0 = bb * TT + qb * 64;

    // load Q tile transposed (consecutive tid -> consecutive d: coalesced)
    for (int i = tid; i < 64 * 64; i += 256) {
        int m = i >> 6, d = i & 63;
        Qs[d * 64 + m] = q[(size_t)(qrow0 + m) * E + h * HD + d];
    }
    __syncthreads();

    float acc[4][4];
    float mr[4], lr[4];
#pragma unroll
    for (int i = 0; i < 4; i++) {
        mr[i] = -INFINITY; lr[i] = 0.f;
#pragma unroll
        for (int j = 0; j < 4; j++) acc[i][j] = 0.f;
    }

    for (int jb = 0; jb <= qb; ++jb) {
        const int krow0 = bb * TT + jb * 64;
        for (int i = tid; i < 64 * 64; i += 256) {
            int m = i >> 6, d = i & 63;
            size_t g = (size_t)(krow0 + m) * KVW + kvh * HD + d;
            Ks[m * 65 + d] = k[g];
            Vs[m * 64 + d] = v[g];
        }
        __syncthreads();

        // S = Q K^T  (4x4 per thread, in registers)
        float s[4][4];
#pragma unroll
        for (int i = 0; i < 4; i++)
#pragma unroll
            for (int j = 0; j < 4; j++) s[i][j] = 0.f;

#pragma unroll 16
        for (int d = 0; d < 64; ++d) {
            float4 qv = *(const float4*)(Qs + d * 64 + r0);
            float qa[4] = {qv.x, qv.y, qv.z, qv.w};
            float kb[4];
#pragma unroll
            for (int j = 0; j < 4; j++) kb[j] = Ks[(c0 + j) * 65 + d];
#pragma unroll
            for (int i = 0; i < 4; i++)
#pragma unroll
                for (int j = 0; j < 4; j++)
                    s[i][j] = fmaf(qa[i], kb[j], s[i][j]);
        }

        const bool diag = (jb == qb);
#pragma unroll
        for (int i = 0; i < 4; i++)
#pragma unroll
            for (int j = 0; j < 4; j++) {
                float val = s[i][j] * 0.125f;
                if (diag && (c0 + j) > (r0 + i)) val = -1e30f;
                s[i][j] = val;
            }

        // online softmax update (per row; stats replicated across 16 lanes)
#pragma unroll
        for (int i = 0; i < 4; i++) {
            float rm = fmaxf(fmaxf(s[i][0], s[i][1]), fmaxf(s[i][2], s[i][3]));
#pragma unroll
            for (int off = 8; off; off >>= 1)
                rm = fmaxf(rm, __shfl_xor_sync(0xffffffffu, rm, off));
            float mnew  = fmaxf(mr[i], rm);
            float alpha = expf(mr[i] - mnew);
            float rs = 0.f;
#pragma unroll
            for (int j = 0; j < 4; j++) {
                s[i][j] = expf(s[i][j] - mnew);
                rs += s[i][j];
            }
#pragma unroll
            for (int off = 8; off; off >>= 1)
                rs += __shfl_xor_sync(0xffffffffu, rs, off);
            lr[i] = lr[i] * alpha + rs;
            mr[i] = mnew;
#pragma unroll
            for (int j = 0; j < 4; j++) acc[i][j] *= alpha;
        }

        __syncthreads();               // done reading Ks as K
        // write P over the K buffer: P[r*65 + c]
#pragma unroll
        for (int i = 0; i < 4; i++)
#pragma unroll
            for (int j = 0; j < 4; j++)
                Ks[(r0 + i) * 65 + (c0 + j)] = s[i][j];
        __syncthreads();

        // O += P V
#pragma unroll 8
        for (int kk = 0; kk < 64; ++kk) {
            float pa[4], vb[4];
#pragma unroll
            for (int i = 0; i < 4; i++) pa[i] = Ks[(r0 + i) * 65 + kk];
#pragma unroll
            for (int j = 0; j < 4; j++) vb[j] = Vs[kk * 64 + c0 + j];
#pragma unroll
            for (int i = 0; i < 4; i++)
#pragma unroll
                for (int j = 0; j < 4; j++)
                    acc[i][j] = fmaf(pa[i], vb[j], acc[i][j]);
        }
        __syncthreads();               // before next tile overwrites Ks/Vs
    }

    // epilogue: normalize and scatter to (b, t, h*HD + d) layout
#pragma unroll
    for (int i = 0; i < 4; i++) {
        float inv = 1.0f / lr[i];
        size_t base = (size_t)(qrow0 + r0 + i) * E + h * HD + c0;
#pragma unroll
        for (int j = 0; j < 4; j++)
            o[base + j] = acc[i][j] * inv;
    }
}

// ---------------- launcher ----------------------------------------------
extern "C" void kernel_launch(void* const* d_in, const int* in_sizes, int n_in,
                              void* d_out, int out_size)
{
    const float* x  = (const float*)d_in[0];
    const float* wq = (const float*)d_in[1];
    const float* bq = (const float*)d_in[2];
    const float* wk = (const float*)d_in[3];
    const float* bk = (const float*)d_in[4];
    const float* wv = (const float*)d_in[5];
    const float* bv = (const float*)d_in[6];
    const float* wo = (const float*)d_in[7];
    const float* bo = (const float*)d_in[8];
    float* out = (float*)d_out;

    float *q, *k, *v, *att;
    cudaGetSymbolAddress((void**)&q,   g_q);
    cudaGetSymbolAddress((void**)&k,   g_k);
    cudaGetSymbolAddress((void**)&v,   g_v);
    cudaGetSymbolAddress((void**)&att, g_att);

    cudaFuncSetAttribute(attn_kernel,
                         cudaFuncAttributeMaxDynamicSharedMemorySize, ATTN_SMEM);

    // projections
    sgemm_bias<<<dim3(E / 128,   MROWS / 128), 256>>>(x, wq, bq, q, MROWS, E,   E);
    sgemm_bias<<<dim3(KVW / 128, MROWS / 128), 256>>>(x, wk, bk, k, MROWS, KVW, E);
    sgemm_bias<<<dim3(KVW / 128, MROWS / 128), 256>>>(x, wv, bv, v, MROWS, KVW, E);

    // RoPE
    {
        int npq = MROWS * (E / 2);     // 2,097,152
        int npk = MROWS * (KVW / 2);   //   524,288
        rope_kernel<<<(npq + 255) / 256, 256>>>(q, E,   npq);
        rope_kernel<<<(npk + 255) / 256, 256>>>(k, KVW, npk);
    }

    // attention
    attn_kernel<<<dim3(TT / 64, NQ, BATCH), 256, ATTN_SMEM>>>(q, k, v, att);

    // output projection
    sgemm_bias<<<dim3(E / 128, MROWS / 128), 256>>>(att, wo, bo, out, MROWS, E, E);
}

// round 14
// speedup vs baseline: 2.0117x; 2.0117x over previous
#include <cuda_runtime.h>
#include <cuda_bf16.h>
#include <math.h>
#include <stdint.h>

#define E      2048
#define TT     1024
#define BATCH  2
#define MROWS  (BATCH * TT)   // 2048
#define NKV    8
#define NQ     32
#define HD     64
#define KVW    (NKV * HD)     // 512

// ---------------- scratch (device globals; no allocations allowed) -------
__device__ float g_q[MROWS * E];
__device__ float g_k[MROWS * KVW];
__device__ float g_v[MROWS * KVW];
__device__ float g_att[MROWS * E];

__device__ __nv_bfloat16 g_xhi[MROWS * E];
__device__ __nv_bfloat16 g_xlo[MROWS * E];
__device__ __nv_bfloat16 g_ahi[MROWS * E];
__device__ __nv_bfloat16 g_alo[MROWS * E];
__device__ __nv_bfloat16 g_wqt_hi[E * E];
__device__ __nv_bfloat16 g_wqt_lo[E * E];
__device__ __nv_bfloat16 g_wkt_hi[KVW * E];
__device__ __nv_bfloat16 g_wkt_lo[KVW * E];
__device__ __nv_bfloat16 g_wvt_hi[KVW * E];
__device__ __nv_bfloat16 g_wvt_lo[KVW * E];
__device__ __nv_bfloat16 g_wot_hi[E * E];
__device__ __nv_bfloat16 g_wot_lo[E * E];

// ---------------- helpers -------------------------------------------------
__device__ __forceinline__ uint32_t smem_u32(const void* p) {
    uint32_t a;
    asm("{ .reg .u64 t; cvta.to.shared.u64 t, %1; cvt.u32.u64 %0, t; }"
        : "=r"(a) : "l"(p));
    return a;
}
__device__ __forceinline__ void cp16(uint32_t dst, const void* src) {
    asm volatile("cp.async.cg.shared.global [%0], [%1], 16;"
                 :: "r"(dst), "l"(src));
}
#define CP_COMMIT() asm volatile("cp.async.commit_group;" ::: "memory")

#define MMA_BF16(acc, a, b)                                                  \
    asm volatile("mma.sync.aligned.m16n8k16.row.col.f32.bf16.bf16.f32 "      \
        "{%0,%1,%2,%3}, {%4,%5,%6,%7}, {%8,%9}, {%0,%1,%2,%3};"              \
        : "+f"((acc)[0]), "+f"((acc)[1]), "+f"((acc)[2]), "+f"((acc)[3])     \
        : "r"((a)[0]), "r"((a)[1]), "r"((a)[2]), "r"((a)[3]),                \
          "r"((b)[0]), "r"((b)[1]))

// ---------------- prep kernels -------------------------------------------
__global__ void split_fp32(const float* __restrict__ X,
                           __nv_bfloat16* __restrict__ hi,
                           __nv_bfloat16* __restrict__ lo, int n4)
{
    int i = blockIdx.x * blockDim.x + threadIdx.x;
    if (i >= n4) return;
    float4 v = ((const float4*)X)[i];
    __align__(8) __nv_bfloat16 h[4], l[4];
    float vv[4] = {v.x, v.y, v.z, v.w};
#pragma unroll
    for (int j = 0; j < 4; j++) {
        h[j] = __float2bfloat16(vv[j]);
        l[j] = __float2bfloat16(vv[j] - __bfloat162float(h[j]));
    }
    ((uint2*)hi)[i] = *(uint2*)h;
    ((uint2*)lo)[i] = *(uint2*)l;
}

__global__ void transpose_split(const float* __restrict__ W,
                                __nv_bfloat16* __restrict__ Thi,
                                __nv_bfloat16* __restrict__ Tlo,
                                int R, int C)
{
    __shared__ float tile[32][33];
    int c0 = blockIdx.x * 32, r0 = blockIdx.y * 32;
    int tx = threadIdx.x, ty = threadIdx.y;   // 32 x 8
#pragma unroll
    for (int i = 0; i < 32; i += 8)
        tile[ty + i][tx] = W[(size_t)(r0 + ty + i) * C + c0 + tx];
    __syncthreads();
#pragma unroll
    for (int i = 0; i < 32; i += 8) {
        float v = tile[tx][ty + i];
        __nv_bfloat16 h = __float2bfloat16(v);
        __nv_bfloat16 l = __float2bfloat16(v - __bfloat162float(h));
        size_t o = (size_t)(c0 + ty + i) * R + r0 + tx;
        Thi[o] = h; Tlo[o] = l;
    }
}

// ---------------- HMMA GEMM ----------------------------------------------
// C[M,N] = (Ahi+Alo)[M,K] * (Bhi+Blo)^T + bias   (B stored [N,K] row-major)
// CTA tile 128x128x32, 8 warps (2x4), warp tile 64x32 (4x4 m16n8k16),
// bf16 3-pass split into shared fp32 accumulators, cp.async double buffer.
#define SSTR        40                       // padded row stride, bf16 units
#define BUF_BYTES   (128 * SSTR * 2)         // 10240 B per operand buffer
#define STAGE_BYTES (4 * BUF_BYTES)          // 40960 B per stage
#define GEMM_SMEM   (2 * STAGE_BYTES)        // 81920 B

__global__ __launch_bounds__(256, 1)
void gemm_hmma(const __nv_bfloat16* __restrict__ Ahi,
               const __nv_bfloat16* __restrict__ Alo,
               const __nv_bfloat16* __restrict__ Bh0,
               const __nv_bfloat16* __restrict__ Bl0,
               const float* __restrict__ bias0, float* __restrict__ C0,
               const __nv_bfloat16* __restrict__ Bh1,
               const __nv_bfloat16* __restrict__ Bl1,
               const float* __restrict__ bias1, float* __restrict__ C1,
               int M, int N, int K)
{
    extern __shared__ __nv_bfloat16 smem[];
    const uint32_t sb = smem_u32(smem);

    const __nv_bfloat16* Bhi  = blockIdx.z ? Bh1   : Bh0;
    const __nv_bfloat16* Blo  = blockIdx.z ? Bl1   : Bl0;
    const float*         bias = blockIdx.z ? bias1 : bias0;
    float*               C    = blockIdx.z ? C1    : C0;

    const int tid  = threadIdx.x;
    const int wid  = tid >> 5;
    const int lane = tid & 31;
    const int wm   = wid >> 2;          // 0..1  (m offset *64)
    const int wn   = wid & 3;           // 0..3  (n offset *32)
    const int g    = lane >> 2;         // 0..7
    const int t4   = lane & 3;          // 0..3
    const int m0   = blockIdx.y * 128;
    const int n0   = blockIdx.x * 128;

    float acc[4][4][4];
#pragma unroll
    for (int i = 0; i < 4; i++)
#pragma unroll
        for (int j = 0; j < 4; j++)
#pragma unroll
            for (int r = 0; r < 4; r++) acc[i][j][r] = 0.f;

    // stage loader: 4 buffers x 512 16B-chunks; 8 cp.async per thread
    auto load_stage = [&](int st, int k0) {
        uint32_t base = sb + st * STAGE_BYTES;
#pragma unroll
        for (int half = 0; half < 2; half++) {
            int t   = tid + half * 256;
            int row = t >> 2;
            int ch  = t & 3;
            uint32_t doff = row * (SSTR * 2) + ch * 16;
            const size_t aoff = (size_t)(m0 + row) * K + k0 + ch * 8;
            const size_t boff = (size_t)(n0 + row) * K + k0 + ch * 8;
            cp16(base + 0 * BUF_BYTES + doff, Ahi + aoff);
            cp16(base + 1 * BUF_BYTES + doff, Alo + aoff);
            cp16(base + 2 * BUF_BYTES + doff, Bhi + boff);
            cp16(base + 3 * BUF_BYTES + doff, Blo + boff);
        }
    };

    const int NC = K / 32;
    load_stage(0, 0);
    CP_COMMIT();

    for (int cidx = 0; cidx < NC; ++cidx) {
        if (cidx + 1 < NC) {
            load_stage((cidx + 1) & 1, (cidx + 1) * 32);
            CP_COMMIT();
            asm volatile("cp.async.wait_group 1;" ::: "memory");
        } else {
            asm volatile("cp.async.wait_group 0;" ::: "memory");
        }
        __syncthreads();

        const __nv_bfloat16* sAh = smem + (cidx & 1) * (STAGE_BYTES / 2);
        const __nv_bfloat16* sAl = sAh + 128 * SSTR;
        const __nv_bfloat16* sBh = sAl + 128 * SSTR;
        const __nv_bfloat16* sBl = sBh + 128 * SSTR;

#pragma unroll
        for (int kk = 0; kk < 32; kk += 16) {
            const int c = kk + t4 * 2;
            uint32_t ah[4][4], al[4][4];
#pragma unroll
            for (int i = 0; i < 4; i++) {
                int r = wm * 64 + i * 16 + g;
                const uint32_t* p0h = (const uint32_t*)(sAh + r * SSTR + c);
                const uint32_t* p8h = (const uint32_t*)(sAh + (r + 8) * SSTR + c);
                ah[i][0] = p0h[0]; ah[i][1] = p8h[0];
                ah[i][2] = p0h[4]; ah[i][3] = p8h[4];
                const uint32_t* p0l = (const uint32_t*)(sAl + r * SSTR + c);
                const uint32_t* p8l = (const uint32_t*)(sAl + (r + 8) * SSTR + c);
                al[i][0] = p0l[0]; al[i][1] = p8l[0];
                al[i][2] = p0l[4]; al[i][3] = p8l[4];
            }
            uint32_t bh[4][2], bl[4][2];
#pragma unroll
            for (int j = 0; j < 4; j++) {
                int n = wn * 32 + j * 8 + g;
                const uint32_t* pbh = (const uint32_t*)(sBh + n * SSTR + c);
                const uint32_t* pbl = (const uint32_t*)(sBl + n * SSTR + c);
                bh[j][0] = pbh[0]; bh[j][1] = pbh[4];
                bl[j][0] = pbl[0]; bl[j][1] = pbl[4];
            }
#pragma unroll
            for (int i = 0; i < 4; i++)
#pragma unroll
                for (int j = 0; j < 4; j++) {
                    MMA_BF16(acc[i][j], ah[i], bh[j]);   // hi * hi
                    MMA_BF16(acc[i][j], ah[i], bl[j]);   // hi * lo
                    MMA_BF16(acc[i][j], al[i], bh[j]);   // lo * hi
                }
        }
        __syncthreads();
    }

    // epilogue
#pragma unroll
    for (int i = 0; i < 4; i++) {
        int row = m0 + wm * 64 + i * 16 + g;
#pragma unroll
        for (int j = 0; j < 4; j++) {
            int col = n0 + wn * 32 + j * 8 + t4 * 2;
            float b0 = bias[col], b1 = bias[col + 1];
            float2 o0 = make_float2(acc[i][j][0] + b0, acc[i][j][1] + b1);
            float2 o1 = make_float2(acc[i][j][2] + b0, acc[i][j][3] + b1);
            *(float2*)(C + (size_t)row * N + col)       = o0;
            *(float2*)(C + (size_t)(row + 8) * N + col) = o1;
        }
    }
}

// ---------------- RoPE (in-place, rotate-half, pos = (t%1024)+1) --------
__global__ void rope_kernel(float* __restrict__ q, int width, int npairs)
{
    int p = blockIdx.x * blockDim.x + threadIdx.x;
    if (p >= npairs) return;
    const int half = width >> 1;
    const int row  = p / half;
    const int rem  = p - row * half;
    const int head = rem >> 5;
    const int c    = rem & 31;
    const int base = row * width + head * HD + c;

    float x0 = q[base];
    float x1 = q[base + 32];
    float pos   = (float)((row & (TT - 1)) + 1);
    float theta = 1.0f / powf(10000.0f, (float)c * (1.0f / 32.0f));
    float ang   = pos * theta;
    float s, co;
    sincosf(ang, &s, &co);
    q[base]      = x0 * co - x1 * s;
    q[base + 32] = x1 * co + x0 * s;
}

// ---------------- Flash attention: 64x64 tiles, fp32 --------------------
#define ATTN_SMEM ((64 * 64 + 64 * 65 + 64 * 64) * 4)

__global__ __launch_bounds__(256)
void attn_kernel(const float* __restrict__ q, const float* __restrict__ k,
                 const float* __restrict__ v, float* __restrict__ o)
{
    extern __shared__ float sm[];
    float* Qs = sm;                 // [64][64]  Qs[d*64 + m]
    float* Ks = sm + 64 * 64;       // [64][65]  Ks[c*65 + d]  (later P)
    float* Vs = Ks + 64 * 65;       // [64][64]

    const int qb  = blockIdx.x;
    const int h   = blockIdx.y;
    const int bb  = blockIdx.z;
    const int kvh = h >> 2;
    const int tid = threadIdx.x;
    const int tx  = tid & 15;
    const int ty  = tid >> 4;
    const int r0  = ty << 2;
    const int c0  = tx << 2;
    const int qrow0 = bb * TT + qb * 64;

    for (int i = tid; i < 64 * 64; i += 256) {
        int m = i >> 6, d = i & 63;
        Qs[d * 64 + m] = q[(size_t)(qrow0 + m) * E + h * HD + d];
    }
    __syncthreads();

    float acc[4][4];
    float mr[4], lr[4];
#pragma unroll
    for (int i = 0; i < 4; i++) {
        mr[i] = -INFINITY; lr[i] = 0.f;
#pragma unroll
        for (int j = 0; j < 4; j++) acc[i][j] = 0.f;
    }

    for (int jb = 0; jb <= qb; ++jb) {
        const int krow0 = bb * TT + jb * 64;
        for (int i = tid; i < 64 * 64; i += 256) {
            int m = i >> 6, d = i & 63;
            size_t gidx = (size_t)(krow0 + m) * KVW + kvh * HD + d;
            Ks[m * 65 + d] = k[gidx];
            Vs[m * 64 + d] = v[gidx];
        }
        __syncthreads();

        float s[4][4];
#pragma unroll
        for (int i = 0; i < 4; i++)
#pragma unroll
            for (int j = 0; j < 4; j++) s[i][j] = 0.f;

#pragma unroll 16
        for (int d = 0; d < 64; ++d) {
            float4 qv = *(const float4*)(Qs + d * 64 + r0);
            float qa[4] = {qv.x, qv.y, qv.z, qv.w};
            float kb[4];
#pragma unroll
            for (int j = 0; j < 4; j++) kb[j] = Ks[(c0 + j) * 65 + d];
#pragma unroll
            for (int i = 0; i < 4; i++)
#pragma unroll
                for (int j = 0; j < 4; j++)
                    s[i][j] = fmaf(qa[i], kb[j], s[i][j]);
        }

        const bool diag = (jb == qb);
#pragma unroll
        for (int i = 0; i < 4; i++)
#pragma unroll
            for (int j = 0; j < 4; j++) {
                float val = s[i][j] * 0.125f;
                if (diag && (c0 + j) > (r0 + i)) val = -1e30f;
                s[i][j] = val;
            }

#pragma unroll
        for (int i = 0; i < 4; i++) {
            float rm = fmaxf(fmaxf(s[i][0], s[i][1]), fmaxf(s[i][2], s[i][3]));
#pragma unroll
            for (int off = 8; off; off >>= 1)
                rm = fmaxf(rm, __shfl_xor_sync(0xffffffffu, rm, off));
            float mnew  = fmaxf(mr[i], rm);
            float alpha = expf(mr[i] - mnew);
            float rs = 0.f;
#pragma unroll
            for (int j = 0; j < 4; j++) {
                s[i][j] = expf(s[i][j] - mnew);
                rs += s[i][j];
            }
#pragma unroll
            for (int off = 8; off; off >>= 1)
                rs += __shfl_xor_sync(0xffffffffu, rs, off);
            lr[i] = lr[i] * alpha + rs;
            mr[i] = mnew;
#pragma unroll
            for (int j = 0; j < 4; j++) acc[i][j] *= alpha;
        }

        __syncthreads();
#pragma unroll
        for (int i = 0; i < 4; i++)
#pragma unroll
            for (int j = 0; j < 4; j++)
                Ks[(r0 + i) * 65 + (c0 + j)] = s[i][j];
        __syncthreads();

#pragma unroll 8
        for (int kk = 0; kk < 64; ++kk) {
            float pa[4], vb[4];
#pragma unroll
            for (int i = 0; i < 4; i++) pa[i] = Ks[(r0 + i) * 65 + kk];
#pragma unroll
            for (int j = 0; j < 4; j++) vb[j] = Vs[kk * 64 + c0 + j];
#pragma unroll
            for (int i = 0; i < 4; i++)
#pragma unroll
                for (int j = 0; j < 4; j++)
                    acc[i][j] = fmaf(pa[i], vb[j], acc[i][j]);
        }
        __syncthreads();
    }

#pragma unroll
    for (int i = 0; i < 4; i++) {
        float inv = 1.0f / lr[i];
        size_t base = (size_t)(qrow0 + r0 + i) * E + h * HD + c0;
#pragma unroll
        for (int j = 0; j < 4; j++)
            o[base + j] = acc[i][j] * inv;
    }
}

// ---------------- launcher ----------------------------------------------
extern "C" void kernel_launch(void* const* d_in, const int* in_sizes, int n_in,
                              void* d_out, int out_size)
{
    const float* x  = (const float*)d_in[0];
    const float* wq = (const float*)d_in[1];
    const float* bq = (const float*)d_in[2];
    const float* wk = (const float*)d_in[3];
    const float* bk = (const float*)d_in[4];
    const float* wv = (const float*)d_in[5];
    const float* bv = (const float*)d_in[6];
    const float* wo = (const float*)d_in[7];
    const float* bo = (const float*)d_in[8];
    float* out = (float*)d_out;

    float *q, *k, *v, *att;
    __nv_bfloat16 *xhi, *xlo, *ahi, *alo;
    __nv_bfloat16 *wqh, *wql, *wkh, *wkl, *wvh, *wvl, *woh, *wol;
    cudaGetSymbolAddress((void**)&q,   g_q);
    cudaGetSymbolAddress((void**)&k,   g_k);
    cudaGetSymbolAddress((void**)&v,   g_v);
    cudaGetSymbolAddress((void**)&att, g_att);
    cudaGetSymbolAddress((void**)&xhi, g_xhi);
    cudaGetSymbolAddress((void**)&xlo, g_xlo);
    cudaGetSymbolAddress((void**)&ahi, g_ahi);
    cudaGetSymbolAddress((void**)&alo, g_alo);
    cudaGetSymbolAddress((void**)&wqh, g_wqt_hi);
    cudaGetSymbolAddress((void**)&wql, g_wqt_lo);
    cudaGetSymbolAddress((void**)&wkh, g_wkt_hi);
    cudaGetSymbolAddress((void**)&wkl, g_wkt_lo);
    cudaGetSymbolAddress((void**)&wvh, g_wvt_hi);
    cudaGetSymbolAddress((void**)&wvl, g_wvt_lo);
    cudaGetSymbolAddress((void**)&woh, g_wot_hi);
    cudaGetSymbolAddress((void**)&wol, g_wot_lo);

    cudaFuncSetAttribute(attn_kernel,
                         cudaFuncAttributeMaxDynamicSharedMemorySize, ATTN_SMEM);
    cudaFuncSetAttribute(gemm_hmma,
                         cudaFuncAttributeMaxDynamicSharedMemorySize, GEMM_SMEM);

    // ---- prep ----
    {
        int n4 = MROWS * E / 4;
        split_fp32<<<(n4 + 255) / 256, 256>>>(x, xhi, xlo, n4);
        transpose_split<<<dim3(E / 32,   E / 32), dim3(32, 8)>>>(wq, wqh, wql, E, E);
        transpose_split<<<dim3(KVW / 32, E / 32), dim3(32, 8)>>>(wk, wkh, wkl, E, KVW);
        transpose_split<<<dim3(KVW / 32, E / 32), dim3(32, 8)>>>(wv, wvh, wvl, E, KVW);
        transpose_split<<<dim3(E / 32,   E / 32), dim3(32, 8)>>>(wo, woh, wol, E, E);
    }

    // ---- projections on tensor pipe (HMMA) ----
    gemm_hmma<<<dim3(E / 128, MROWS / 128, 1), 256, GEMM_SMEM>>>(
        xhi, xlo, wqh, wql, bq, q, wqh, wql, bq, q, MROWS, E, E);
    gemm_hmma<<<dim3(KVW / 128, MROWS / 128, 2), 256, GEMM_SMEM>>>(
        xhi, xlo, wkh, wkl, bk, k, wvh, wvl, bv, v, MROWS, KVW, E);

    // ---- RoPE ----
    {
        int npq = MROWS * (E / 2);
        int npk = MROWS * (KVW / 2);
        rope_kernel<<<(npq + 255) / 256, 256>>>(q, E,   npq);
        rope_kernel<<<(npk + 255) / 256, 256>>>(k, KVW, npk);
    }

    // ---- attention (fp32 SIMT) ----
    attn_kernel<<<dim3(TT / 64, NQ, BATCH), 256, ATTN_SMEM>>>(q, k, v, att);

    // ---- output projection ----
    {
        int n4 = MROWS * E / 4;
        split_fp32<<<(n4 + 255) / 256, 256>>>(att, ahi, alo, n4);
    }
    gemm_hmma<<<dim3(E / 128, MROWS / 128, 1), 256, GEMM_SMEM>>>(
        ahi, alo, woh, wol, bo, out, woh, wol, bo, out, MROWS, E, E);
}

// round 15
// speedup vs baseline: 2.0166x; 1.0024x over previous
#include <cuda_runtime.h>
#include <cuda_bf16.h>
#include <math.h>
#include <stdint.h>

#define E      2048
#define TT     1024
#define BATCH  2
#define MROWS  (BATCH * TT)   // 2048
#define NKV    8
#define NQ     32
#define HD     64
#define KVW    (NKV * HD)     // 512

// ---------------- scratch (device globals; no allocations allowed) -------
__device__ float g_q[MROWS * E];
__device__ float g_k[MROWS * KVW];
__device__ float g_v[MROWS * KVW];
__device__ float g_att[MROWS * E];

__device__ __nv_bfloat16 g_xhi[MROWS * E];
__device__ __nv_bfloat16 g_xlo[MROWS * E];
__device__ __nv_bfloat16 g_ahi[MROWS * E];
__device__ __nv_bfloat16 g_alo[MROWS * E];
__device__ __nv_bfloat16 g_wqt_hi[E * E];
__device__ __nv_bfloat16 g_wqt_lo[E * E];
__device__ __nv_bfloat16 g_wkt_hi[KVW * E];
__device__ __nv_bfloat16 g_wkt_lo[KVW * E];
__device__ __nv_bfloat16 g_wvt_hi[KVW * E];
__device__ __nv_bfloat16 g_wvt_lo[KVW * E];
__device__ __nv_bfloat16 g_wot_hi[E * E];
__device__ __nv_bfloat16 g_wot_lo[E * E];

// ---------------- helpers -------------------------------------------------
__device__ __forceinline__ uint32_t smem_u32(const void* p) {
    uint32_t a;
    asm("{ .reg .u64 t; cvta.to.shared.u64 t, %1; cvt.u32.u64 %0, t; }"
        : "=r"(a) : "l"(p));
    return a;
}
__device__ __forceinline__ void cp16(uint32_t dst, const void* src) {
    asm volatile("cp.async.cg.shared.global [%0], [%1], 16;"
                 :: "r"(dst), "l"(src));
}
#define CP_COMMIT() asm volatile("cp.async.commit_group;" ::: "memory")

#define MMA_BF16(acc, a, b)                                                  \
    asm volatile("mma.sync.aligned.m16n8k16.row.col.f32.bf16.bf16.f32 "      \
        "{%0,%1,%2,%3}, {%4,%5,%6,%7}, {%8,%9}, {%0,%1,%2,%3};"              \
        : "+f"((acc)[0]), "+f"((acc)[1]), "+f"((acc)[2]), "+f"((acc)[3])     \
        : "r"((a)[0]), "r"((a)[1]), "r"((a)[2]), "r"((a)[3]),                \
          "r"((b)[0]), "r"((b)[1]))

// ---------------- prep kernels -------------------------------------------
__global__ void split_fp32(const float* __restrict__ X,
                           __nv_bfloat16* __restrict__ hi,
                           __nv_bfloat16* __restrict__ lo, int n4)
{
    int i = blockIdx.x * blockDim.x + threadIdx.x;
    if (i >= n4) return;
    float4 v = ((const float4*)X)[i];
    __align__(8) __nv_bfloat16 h[4], l[4];
    float vv[4] = {v.x, v.y, v.z, v.w};
#pragma unroll
    for (int j = 0; j < 4; j++) {
        h[j] = __float2bfloat16(vv[j]);
        l[j] = __float2bfloat16(vv[j] - __bfloat162float(h[j]));
    }
    ((uint2*)hi)[i] = *(uint2*)h;
    ((uint2*)lo)[i] = *(uint2*)l;
}

__global__ void transpose_split(const float* __restrict__ W,
                                __nv_bfloat16* __restrict__ Thi,
                                __nv_bfloat16* __restrict__ Tlo,
                                int R, int C)
{
    __shared__ float tile[32][33];
    int c0 = blockIdx.x * 32, r0 = blockIdx.y * 32;
    int tx = threadIdx.x, ty = threadIdx.y;   // 32 x 8
#pragma unroll
    for (int i = 0; i < 32; i += 8)
        tile[ty + i][tx] = W[(size_t)(r0 + ty + i) * C + c0 + tx];
    __syncthreads();
#pragma unroll
    for (int i = 0; i < 32; i += 8) {
        float v = tile[tx][ty + i];
        __nv_bfloat16 h = __float2bfloat16(v);
        __nv_bfloat16 l = __float2bfloat16(v - __bfloat162float(h));
        size_t o = (size_t)(c0 + ty + i) * R + r0 + tx;
        Thi[o] = h; Tlo[o] = l;
    }
}

// ---------------- HMMA GEMM ----------------------------------------------
// C[M,N] = (Ahi+Alo)[M,K] * (Bhi+Blo)^T + bias   (B stored [N,K] row-major)
// CTA tile 128x128x32, 8 warps (2x4), warp tile 64x32 (4x4 m16n8k16),
// bf16 3-pass split into shared fp32 accumulators, cp.async double buffer.
#define SSTR        40                       // padded row stride, bf16 units
#define BUF_BYTES   (128 * SSTR * 2)         // 10240 B per operand buffer
#define STAGE_BYTES (4 * BUF_BYTES)          // 40960 B per stage
#define GEMM_SMEM   (2 * STAGE_BYTES)        // 81920 B

__global__ __launch_bounds__(256, 1)
void gemm_hmma(const __nv_bfloat16* __restrict__ Ahi,
               const __nv_bfloat16* __restrict__ Alo,
               const __nv_bfloat16* __restrict__ Bh0,
               const __nv_bfloat16* __restrict__ Bl0,
               const float* __restrict__ bias0, float* __restrict__ C0,
               const __nv_bfloat16* __restrict__ Bh1,
               const __nv_bfloat16* __restrict__ Bl1,
               const float* __restrict__ bias1, float* __restrict__ C1,
               int M, int N, int K)
{
    extern __shared__ __nv_bfloat16 smem[];
    const uint32_t sb = smem_u32(smem);

    const __nv_bfloat16* Bhi  = blockIdx.z ? Bh1   : Bh0;
    const __nv_bfloat16* Blo  = blockIdx.z ? Bl1   : Bl0;
    const float*         bias = blockIdx.z ? bias1 : bias0;
    float*               C    = blockIdx.z ? C1    : C0;

    const int tid  = threadIdx.x;
    const int wid  = tid >> 5;
    const int lane = tid & 31;
    const int wm   = wid >> 2;          // 0..1  (m offset *64)
    const int wn   = wid & 3;           // 0..3  (n offset *32)
    const int g    = lane >> 2;         // 0..7
    const int t4   = lane & 3;          // 0..3
    const int m0   = blockIdx.y * 128;
    const int n0   = blockIdx.x * 128;

    float acc[4][4][4];
#pragma unroll
    for (int i = 0; i < 4; i++)
#pragma unroll
        for (int j = 0; j < 4; j++)
#pragma unroll
            for (int r = 0; r < 4; r++) acc[i][j][r] = 0.f;

    // stage loader: 4 buffers x 512 16B-chunks; 8 cp.async per thread
    auto load_stage = [&](int st, int k0) {
        uint32_t base = sb + st * STAGE_BYTES;
#pragma unroll
        for (int half = 0; half < 2; half++) {
            int t   = tid + half * 256;
            int row = t >> 2;
            int ch  = t & 3;
            uint32_t doff = row * (SSTR * 2) + ch * 16;
            const size_t aoff = (size_t)(m0 + row) * K + k0 + ch * 8;
            const size_t boff = (size_t)(n0 + row) * K + k0 + ch * 8;
            cp16(base + 0 * BUF_BYTES + doff, Ahi + aoff);
            cp16(base + 1 * BUF_BYTES + doff, Alo + aoff);
            cp16(base + 2 * BUF_BYTES + doff, Bhi + boff);
            cp16(base + 3 * BUF_BYTES + doff, Blo + boff);
        }
    };

    const int NC = K / 32;
    load_stage(0, 0);
    CP_COMMIT();

    for (int cidx = 0; cidx < NC; ++cidx) {
        if (cidx + 1 < NC) {
            load_stage((cidx + 1) & 1, (cidx + 1) * 32);
            CP_COMMIT();
            asm volatile("cp.async.wait_group 1;" ::: "memory");
        } else {
            asm volatile("cp.async.wait_group 0;" ::: "memory");
        }
        __syncthreads();

        const __nv_bfloat16* sAh = smem + (cidx & 1) * (STAGE_BYTES / 2);
        const __nv_bfloat16* sAl = sAh + 128 * SSTR;
        const __nv_bfloat16* sBh = sAl + 128 * SSTR;
        const __nv_bfloat16* sBl = sBh + 128 * SSTR;

#pragma unroll
        for (int kk = 0; kk < 32; kk += 16) {
            const int c = kk + t4 * 2;
            uint32_t ah[4][4], al[4][4];
#pragma unroll
            for (int i = 0; i < 4; i++) {
                int r = wm * 64 + i * 16 + g;
                const uint32_t* p0h = (const uint32_t*)(sAh + r * SSTR + c);
                const uint32_t* p8h = (const uint32_t*)(sAh + (r + 8) * SSTR + c);
                ah[i][0] = p0h[0]; ah[i][1] = p8h[0];
                ah[i][2] = p0h[4]; ah[i][3] = p8h[4];
                const uint32_t* p0l = (const uint32_t*)(sAl + r * SSTR + c);
                const uint32_t* p8l = (const uint32_t*)(sAl + (r + 8) * SSTR + c);
                al[i][0] = p0l[0]; al[i][1] = p8l[0];
                al[i][2] = p0l[4]; al[i][3] = p8l[4];
            }
            uint32_t bh[4][2], bl[4][2];
#pragma unroll
            for (int j = 0; j < 4; j++) {
                int n = wn * 32 + j * 8 + g;
                const uint32_t* pbh = (const uint32_t*)(sBh + n * SSTR + c);
                const uint32_t* pbl = (const uint32_t*)(sBl + n * SSTR + c);
                bh[j][0] = pbh[0]; bh[j][1] = pbh[4];
                bl[j][0] = pbl[0]; bl[j][1] = pbl[4];
            }
#pragma unroll
            for (int i = 0; i < 4; i++)
#pragma unroll
                for (int j = 0; j < 4; j++) {
                    MMA_BF16(acc[i][j], ah[i], bh[j]);   // hi * hi
                    MMA_BF16(acc[i][j], ah[i], bl[j]);   // hi * lo
                    MMA_BF16(acc[i][j], al[i], bh[j]);   // lo * hi
                }
        }
        __syncthreads();
    }

    // epilogue
#pragma unroll
    for (int i = 0; i < 4; i++) {
        int row = m0 + wm * 64 + i * 16 + g;
#pragma unroll
        for (int j = 0; j < 4; j++) {
            int col = n0 + wn * 32 + j * 8 + t4 * 2;
            float b0 = bias[col], b1 = bias[col + 1];
            float2 o0 = make_float2(acc[i][j][0] + b0, acc[i][j][1] + b1);
            float2 o1 = make_float2(acc[i][j][2] + b0, acc[i][j][3] + b1);
            *(float2*)(C + (size_t)row * N + col)       = o0;
            *(float2*)(C + (size_t)(row + 8) * N + col) = o1;
        }
    }
}

// ---------------- RoPE (in-place, rotate-half, pos = (t%1024)+1) --------
__global__ void rope_kernel(float* __restrict__ q, int width, int npairs)
{
    int p = blockIdx.x * blockDim.x + threadIdx.x;
    if (p >= npairs) return;
    const int half = width >> 1;
    const int row  = p / half;
    const int rem  = p - row * half;
    const int head = rem >> 5;
    const int c    = rem & 31;
    const int base = row * width + head * HD + c;

    float x0 = q[base];
    float x1 = q[base + 32];
    float pos   = (float)((row & (TT - 1)) + 1);
    float theta = 1.0f / powf(10000.0f, (float)c * (1.0f / 32.0f));
    float ang   = pos * theta;
    float s, co;
    sincosf(ang, &s, &co);
    q[base]      = x0 * co - x1 * s;
    q[base + 32] = x1 * co + x0 * s;
}

// ---------------- Flash attention: 64x64 tiles, fp32 --------------------
#define ATTN_SMEM ((64 * 64 + 64 * 65 + 64 * 64) * 4)

__global__ __launch_bounds__(256)
void attn_kernel(const float* __restrict__ q, const float* __restrict__ k,
                 const float* __restrict__ v, float* __restrict__ o)
{
    extern __shared__ float sm[];
    float* Qs = sm;                 // [64][64]  Qs[d*64 + m]
    float* Ks = sm + 64 * 64;       // [64][65]  Ks[c*65 + d]  (later P)
    float* Vs = Ks + 64 * 65;       // [64][64]

    const int qb  = blockIdx.x;
    const int h   = blockIdx.y;
    const int bb  = blockIdx.z;
    const int kvh = h >> 2;
    const int tid = threadIdx.x;
    const int tx  = tid & 15;
    const int ty  = tid >> 4;
    const int r0  = ty << 2;
    const int c0  = tx << 2;
    const int qrow0 = bb * TT + qb * 64;

    for (int i = tid; i < 64 * 64; i += 256) {
        int m = i >> 6, d = i & 63;
        Qs[d * 64 + m] = q[(size_t)(qrow0 + m) * E + h * HD + d];
    }
    __syncthreads();

    float acc[4][4];
    float mr[4], lr[4];
#pragma unroll
    for (int i = 0; i < 4; i++) {
        mr[i] = -INFINITY; lr[i] = 0.f;
#pragma unroll
        for (int j = 0; j < 4; j++) acc[i][j] = 0.f;
    }

    for (int jb = 0; jb <= qb; ++jb) {
        const int krow0 = bb * TT + jb * 64;
        for (int i = tid; i < 64 * 64; i += 256) {
            int m = i >> 6, d = i & 63;
            size_t gidx = (size_t)(krow0 + m) * KVW + kvh * HD + d;
            Ks[m * 65 + d] = k[gidx];
            Vs[m * 64 + d] = v[gidx];
        }
        __syncthreads();

        float s[4][4];
#pragma unroll
        for (int i = 0; i < 4; i++)
#pragma unroll
            for (int j = 0; j < 4; j++) s[i][j] = 0.f;

#pragma unroll 16
        for (int d = 0; d < 64; ++d) {
            float4 qv = *(const float4*)(Qs + d * 64 + r0);
            float qa[4] = {qv.x, qv.y, qv.z, qv.w};
            float kb[4];
#pragma unroll
            for (int j = 0; j < 4; j++) kb[j] = Ks[(c0 + j) * 65 + d];
#pragma unroll
            for (int i = 0; i < 4; i++)
#pragma unroll
                for (int j = 0; j < 4; j++)
                    s[i][j] = fmaf(qa[i], kb[j], s[i][j]);
        }

        const bool diag = (jb == qb);
#pragma unroll
        for (int i = 0; i < 4; i++)
#pragma unroll
            for (int j = 0; j < 4; j++) {
                float val = s[i][j] * 0.125f;
                if (diag && (c0 + j) > (r0 + i)) val = -1e30f;
                s[i][j] = val;
            }

#pragma unroll
        for (int i = 0; i < 4; i++) {
            float rm = fmaxf(fmaxf(s[i][0], s[i][1]), fmaxf(s[i][2], s[i][3]));
#pragma unroll
            for (int off = 8; off; off >>= 1)
                rm = fmaxf(rm, __shfl_xor_sync(0xffffffffu, rm, off));
            float mnew  = fmaxf(mr[i], rm);
            float alpha = expf(mr[i] - mnew);
            float rs = 0.f;
#pragma unroll
            for (int j = 0; j < 4; j++) {
                s[i][j] = expf(s[i][j] - mnew);
                rs += s[i][j];
            }
#pragma unroll
            for (int off = 8; off; off >>= 1)
                rs += __shfl_xor_sync(0xffffffffu, rs, off);
            lr[i] = lr[i] * alpha + rs;
            mr[i] = mnew;
#pragma unroll
            for (int j = 0; j < 4; j++) acc[i][j] *= alpha;
        }

        __syncthreads();
#pragma unroll
        for (int i = 0; i < 4; i++)
#pragma unroll
            for (int j = 0; j < 4; j++)
                Ks[(r0 + i) * 65 + (c0 + j)] = s[i][j];
        __syncthreads();

#pragma unroll 8
        for (int kk = 0; kk < 64; ++kk) {
            float pa[4], vb[4];
#pragma unroll
            for (int i = 0; i < 4; i++) pa[i] = Ks[(r0 + i) * 65 + kk];
#pragma unroll
            for (int j = 0; j < 4; j++) vb[j] = Vs[kk * 64 + c0 + j];
#pragma unroll
            for (int i = 0; i < 4; i++)
#pragma unroll
                for (int j = 0; j < 4; j++)
                    acc[i][j] = fmaf(pa[i], vb[j], acc[i][j]);
        }
        __syncthreads();
    }

#pragma unroll
    for (int i = 0; i < 4; i++) {
        float inv = 1.0f / lr[i];
        size_t base = (size_t)(qrow0 + r0 + i) * E + h * HD + c0;
#pragma unroll
        for (int j = 0; j < 4; j++)
            o[base + j] = acc[i][j] * inv;
    }
}

// ---------------- launcher ----------------------------------------------
extern "C" void kernel_launch(void* const* d_in, const int* in_sizes, int n_in,
                              void* d_out, int out_size)
{
    const float* x  = (const float*)d_in[0];
    const float* wq = (const float*)d_in[1];
    const float* bq = (const float*)d_in[2];
    const float* wk = (const float*)d_in[3];
    const float* bk = (const float*)d_in[4];
    const float* wv = (const float*)d_in[5];
    const float* bv = (const float*)d_in[6];
    const float* wo = (const float*)d_in[7];
    const float* bo = (const float*)d_in[8];
    float* out = (float*)d_out;

    float *q, *k, *v, *att;
    __nv_bfloat16 *xhi, *xlo, *ahi, *alo;
    __nv_bfloat16 *wqh, *wql, *wkh, *wkl, *wvh, *wvl, *woh, *wol;
    cudaGetSymbolAddress((void**)&q,   g_q);
    cudaGetSymbolAddress((void**)&k,   g_k);
    cudaGetSymbolAddress((void**)&v,   g_v);
    cudaGetSymbolAddress((void**)&att, g_att);
    cudaGetSymbolAddress((void**)&xhi, g_xhi);
    cudaGetSymbolAddress((void**)&xlo, g_xlo);
    cudaGetSymbolAddress((void**)&ahi, g_ahi);
    cudaGetSymbolAddress((void**)&alo, g_alo);
    cudaGetSymbolAddress((void**)&wqh, g_wqt_hi);
    cudaGetSymbolAddress((void**)&wql, g_wqt_lo);
    cudaGetSymbolAddress((void**)&wkh, g_wkt_hi);
    cudaGetSymbolAddress((void**)&wkl, g_wkt_lo);
    cudaGetSymbolAddress((void**)&wvh, g_wvt_hi);
    cudaGetSymbolAddress((void**)&wvl, g_wvt_lo);
    cudaGetSymbolAddress((void**)&woh, g_wot_hi);
    cudaGetSymbolAddress((void**)&wol, g_wot_lo);

    cudaFuncSetAttribute(attn_kernel,
                         cudaFuncAttributeMaxDynamicSharedMemorySize, ATTN_SMEM);
    cudaFuncSetAttribute(gemm_hmma,
                         cudaFuncAttributeMaxDynamicSharedMemorySize, GEMM_SMEM);

    // ---- prep ----
    {
        int n4 = MROWS * E / 4;
        split_fp32<<<(n4 + 255) / 256, 256>>>(x, xhi, xlo, n4);
        transpose_split<<<dim3(E / 32,   E / 32), dim3(32, 8)>>>(wq, wqh, wql, E, E);
        transpose_split<<<dim3(KVW / 32, E / 32), dim3(32, 8)>>>(wk, wkh, wkl, E, KVW);
        transpose_split<<<dim3(KVW / 32, E / 32), dim3(32, 8)>>>(wv, wvh, wvl, E, KVW);
        transpose_split<<<dim3(E / 32,   E / 32), dim3(32, 8)>>>(wo, woh, wol, E, E);
    }

    // ---- projections on tensor pipe (HMMA) ----
    gemm_hmma<<<dim3(E / 128, MROWS / 128, 1), 256, GEMM_SMEM>>>(
        xhi, xlo, wqh, wql, bq, q, wqh, wql, bq, q, MROWS, E, E);
    gemm_hmma<<<dim3(KVW / 128, MROWS / 128, 2), 256, GEMM_SMEM>>>(
        xhi, xlo, wkh, wkl, bk, k, wvh, wvl, bv, v, MROWS, KVW, E);

    // ---- RoPE ----
    {
        int npq = MROWS * (E / 2);
        int npk = MROWS * (KVW / 2);
        rope_kernel<<<(npq + 255) / 256, 256>>>(q, E,   npq);
        rope_kernel<<<(npk + 255) / 256, 256>>>(k, KVW, npk);
    }

    // ---- attention (fp32 SIMT) ----
    attn_kernel<<<dim3(TT / 64, NQ, BATCH), 256, ATTN_SMEM>>>(q, k, v, att);

    // ---- output projection ----
    {
        int n4 = MROWS * E / 4;
        split_fp32<<<(n4 + 255) / 256, 256>>>(att, ahi, alo, n4);
    }
    gemm_hmma<<<dim3(E / 128, MROWS / 128, 1), 256, GEMM_SMEM>>>(
        ahi, alo, woh, wol, bo, out, woh, wol, bo, out, MROWS, E, E);
}